// round 2
// baseline (speedup 1.0000x reference)
#include <cuda_runtime.h>
#include <cuda_bf16.h>
#include <cstdint>

// Problem shape: N=40000 nodes, F_in=256, F_out=128, E=640000 edges.
static constexpr int MAXN = 40000;
static constexpr int MAXE = 640000;

// Scratch (allocation-free rule: __device__ globals)
__device__ int    g_is64;               // 1 if edge_index is int64, 0 if int32
__device__ int    g_cnt[MAXN];          // in-degree (edges only)
__device__ int    g_cur[MAXN];          // scatter cursors
__device__ int    g_rowptr[MAXN + 1];   // CSR row pointers (by dst)
__device__ float  g_dinv[MAXN];         // rsqrt(deg+1)
__device__ int    g_srcid[MAXE];        // CSR column (source node) ids
__device__ float4 g_xws[MAXN * 32];     // dinv[i] * (x @ W)[i], 32 float4 per row

// ---------------------------------------------------------------------------
// 0) dtype probe: int64 indices in [0,40000) have zero high words.
//    Inspect first 2048 int32 words (8 KB, safely inside either buffer size).
__global__ void detect_kernel(const int* __restrict__ ei32) {
    __shared__ int red[8];
    int tid = threadIdx.x;                       // 256 threads
    int acc = 0;
    for (int i = tid; i < 1024; i += 256)
        acc |= ei32[2 * i + 1];                  // odd words = int64 high halves
    #pragma unroll
    for (int off = 16; off > 0; off >>= 1)
        acc |= __shfl_down_sync(0xFFFFFFFFu, acc, off);
    if ((tid & 31) == 0) red[tid >> 5] = acc;
    __syncthreads();
    if (tid == 0) {
        int r = 0;
        #pragma unroll
        for (int w = 0; w < 8; w++) r |= red[w];
        g_is64 = (r == 0) ? 1 : 0;
    }
}

__device__ __forceinline__ int load_idx(const void* ei, long long i, int is64) {
    if (is64) return (int)((const long long*)ei)[i];
    return ((const int*)ei)[i];
}

// 1) zero counters
__global__ void zero_kernel(int N) {
    int i = blockIdx.x * blockDim.x + threadIdx.x;
    if (i < N) { g_cnt[i] = 0; g_cur[i] = 0; }
}

// 2) histogram of dst (dst = elements [E, 2E) of edge_index)
__global__ void count_kernel(const void* __restrict__ ei, int E, int N) {
    int e = blockIdx.x * blockDim.x + threadIdx.x;
    if (e < E) {
        int is64 = g_is64;
        unsigned d = (unsigned)load_idx(ei, (long long)E + e, is64);
        if (d < (unsigned)N) atomicAdd(&g_cnt[d], 1);
    }
}

// 3) dinv = rsqrt(in_degree + 1)   (self-loop included)
__global__ void dinv_kernel(int N) {
    int i = blockIdx.x * blockDim.x + threadIdx.x;
    if (i < N) g_dinv[i] = rsqrtf((float)g_cnt[i] + 1.0f);
}

// 4) exclusive scan of g_cnt -> g_rowptr (single block, 1024 threads)
__global__ void __launch_bounds__(1024) scan_kernel(int N) {
    __shared__ int shw[32];
    __shared__ int carry;
    int tid = threadIdx.x, lane = tid & 31, warp = tid >> 5;
    if (tid == 0) { carry = 0; g_rowptr[0] = 0; }
    __syncthreads();
    for (int base = 0; base < N; base += 1024) {
        int i = base + tid;
        int v = (i < N) ? g_cnt[i] : 0;
        int s = v;
        #pragma unroll
        for (int off = 1; off < 32; off <<= 1) {
            int t = __shfl_up_sync(0xFFFFFFFFu, s, off);
            if (lane >= off) s += t;
        }
        if (lane == 31) shw[warp] = s;
        __syncthreads();
        if (warp == 0) {
            int ws = shw[lane];
            #pragma unroll
            for (int off = 1; off < 32; off <<= 1) {
                int t = __shfl_up_sync(0xFFFFFFFFu, ws, off);
                if (lane >= off) ws += t;
            }
            shw[lane] = ws;
        }
        __syncthreads();
        int incl = s + (warp > 0 ? shw[warp - 1] : 0) + carry;
        if (i < N) g_rowptr[i + 1] = incl;
        __syncthreads();
        if (tid == 0) carry += shw[31];
        __syncthreads();
    }
}

// 5) scatter edge source ids into CSR slots
__global__ void scatter_kernel(const void* __restrict__ ei, int E, int N) {
    int e = blockIdx.x * blockDim.x + threadIdx.x;
    if (e < E) {
        int is64 = g_is64;
        unsigned d = (unsigned)load_idx(ei, (long long)E + e, is64);
        unsigned s = (unsigned)load_idx(ei, e, is64);
        if (d < (unsigned)N && s < (unsigned)N) {
            int pos = g_rowptr[d] + atomicAdd(&g_cur[d], 1);
            g_srcid[pos] = (int)s;
        }
    }
}

// ---------------------------------------------------------------------------
// 6) GEMM: xws[i,:] = dinv[i] * (x[i,:] @ W)    x:[N,256]  W:[256,128]
//    Tile: 32 rows x 128 cols per block, BK=32, 256 threads,
//    thread tile = 4 rows x 4 cols (float4 on W).
__global__ void __launch_bounds__(256) gemm_kernel(const float* __restrict__ x,
                                                   const float* __restrict__ W,
                                                   int N) {
    __shared__ float  xs[32][33];      // [row][k]
    __shared__ float4 ws4[32][32];     // [k][col-group]

    const int tid = threadIdx.x;
    const int jc  = tid & 31;          // col group (float4): cols jc*4..jc*4+3
    const int rg  = tid >> 5;          // 0..7
    const int r0  = rg * 4;            // thread's first row in tile
    const int row0 = blockIdx.x * 32;

    const float4* W4 = (const float4*)W;

    float4 acc[4];
    #pragma unroll
    for (int r = 0; r < 4; r++) acc[r] = make_float4(0.f, 0.f, 0.f, 0.f);

    for (int k0 = 0; k0 < 256; k0 += 32) {
        {
            int k  = tid & 31;
            int rb = tid >> 5;
            #pragma unroll
            for (int i = 0; i < 4; i++) {
                int r = rb + 8 * i;
                xs[r][k] = x[(size_t)(row0 + r) * 256 + k0 + k];
            }
        }
        {
            int kb = tid >> 5;
            #pragma unroll
            for (int i = 0; i < 4; i++) {
                int k = kb + 8 * i;
                ws4[k][jc] = W4[(size_t)(k0 + k) * 32 + jc];
            }
        }
        __syncthreads();
        #pragma unroll
        for (int kk = 0; kk < 32; kk++) {
            float4 wv = ws4[kk][jc];
            #pragma unroll
            for (int r = 0; r < 4; r++) {
                float xv = xs[r0 + r][kk];
                acc[r].x += xv * wv.x;
                acc[r].y += xv * wv.y;
                acc[r].z += xv * wv.z;
                acc[r].w += xv * wv.w;
            }
        }
        __syncthreads();
    }

    #pragma unroll
    for (int r = 0; r < 4; r++) {
        int row = row0 + r0 + r;
        if (row < N) {
            float di = g_dinv[row];
            float4 v = acc[r];
            v.x *= di; v.y *= di; v.z *= di; v.w *= di;
            g_xws[(size_t)row * 32 + jc] = v;
        }
    }
}

// ---------------------------------------------------------------------------
// 7) aggregation: one warp per node.
//    out[i] = relu( dinv[i] * ( xws[i] + sum_{e: dst=i} xws[src[e]] ) + b )
__global__ void __launch_bounds__(256) agg_kernel(const float* __restrict__ b,
                                                  float* __restrict__ out, int N) {
    int warp = (blockIdx.x * blockDim.x + threadIdx.x) >> 5;
    int lane = threadIdx.x & 31;
    if (warp >= N) return;
    int node = warp;

    float4 acc = g_xws[(size_t)node * 32 + lane];   // self-loop contribution

    int e   = g_rowptr[node];
    int end = g_rowptr[node + 1];
    for (; e < end; e++) {
        int s = g_srcid[e];
        float4 v = g_xws[(size_t)s * 32 + lane];
        acc.x += v.x; acc.y += v.y; acc.z += v.z; acc.w += v.w;
    }

    float di = g_dinv[node];
    float4 bb = ((const float4*)b)[lane];
    float4 o;
    o.x = fmaxf(di * acc.x + bb.x, 0.f);
    o.y = fmaxf(di * acc.y + bb.y, 0.f);
    o.z = fmaxf(di * acc.z + bb.z, 0.f);
    o.w = fmaxf(di * acc.w + bb.w, 0.f);
    ((float4*)out)[(size_t)node * 32 + lane] = o;
}

// ---------------------------------------------------------------------------
extern "C" void kernel_launch(void* const* d_in, const int* in_sizes, int n_in,
                              void* d_out, int out_size) {
    const float* x  = (const float*)d_in[0];
    const void*  ei = d_in[1];                 // [2, E] int32 or int64 (probed)
    const float* W  = (const float*)d_in[2];
    const float* b  = (const float*)d_in[3];
    float*       out = (float*)d_out;

    const int N = in_sizes[0] / 256;   // 40000
    const int E = in_sizes[1] / 2;     // 640000

    detect_kernel<<<1, 256>>>((const int*)ei);
    zero_kernel<<<(N + 255) / 256, 256>>>(N);
    count_kernel<<<(E + 255) / 256, 256>>>(ei, E, N);
    dinv_kernel<<<(N + 255) / 256, 256>>>(N);
    scan_kernel<<<1, 1024>>>(N);
    scatter_kernel<<<(E + 255) / 256, 256>>>(ei, E, N);
    gemm_kernel<<<(N + 31) / 32, 256>>>(x, W, N);
    agg_kernel<<<(N * 32 + 255) / 256, 256>>>(b, out, N);
}